// round 9
// baseline (speedup 1.0000x reference)
#include <cuda_runtime.h>
#include <cstdint>
#include <cfloat>

#define KC 120
#define DC 128
#define NMAX 262144
#define TILE_M 128
#define DCH 32
#define NCHUNK 4
#define SROW 121          // S row stride (floats), odd => conflict-free column scans

typedef unsigned long long u64;

// ---------------- device scratch ----------------
__device__ float  g_cent[2][KC * DC];
__device__ float  g_csq[2][KC];
__device__ float  g_sums[KC * DC];
__device__ float  g_counts[KC];
__device__ int    g_labels[2][NMAX];
__device__ double g_acc[2];

// single dynamic-smem symbol shared by all kernels (cast locally)
extern __shared__ char dyn_smem[];

// ---------------- f32x2 helpers ----------------
__device__ __forceinline__ u64 pack2(float a, float b) {
    u64 r;
    asm("mov.b64 %0, {%1, %2};" : "=l"(r)
        : "r"(__float_as_uint(a)), "r"(__float_as_uint(b)));
    return r;
}
__device__ __forceinline__ void fma2(u64& d, u64 a, u64 b) {
    asm("fma.rn.f32x2 %0, %1, %2, %0;" : "+l"(d) : "l"(a), "l"(b));
}
__device__ __forceinline__ float2 unpack2(u64 a) {
    unsigned lo, hi;
    asm("mov.b64 {%0, %1}, %2;" : "=r"(lo), "=r"(hi) : "l"(a));
    return make_float2(__uint_as_float(lo), __uint_as_float(hi));
}

// ---------------- smem layout (gemm kernel) ----------------
#define OFF_CSQ 0                      // 128 floats
#define OFF_RED 512                    // 8 floats
#define OFF_S   1024                   // 128*121 floats = 61952 B (epilogue, overlaps XD/CP)
#define OFF_XD  1024                   // 32*128 u64 = 32768 B
#define OFF_CP  (1024 + 32768)         // 32*64  u64 = 16384 B
#define GEMM_SMEM (1024 + TILE_M * SROW * 4)   // 62976 B

// ================= register-tiled FFMA2 GEMM + head =================
// dot[p][k] = x_p . c_k for a 128-point tile vs all 120 centroids.
// mode 0: argmin_k (csq[k] - 2*dot) -> g_labels[set]
// mode 1: CE_i = logsumexp(2.5*dot) - 2.5*dot[lab_i], summed -> g_acc[aidx]
__global__ __launch_bounds__(256, 2)
void gemm_head_kernel(const float* __restrict__ x, int set, int mode, int aidx, int N) {
    char* sm = dyn_smem;
    float* csq_s = (float*)(sm + OFF_CSQ);
    u64*   xd    = (u64*)(sm + OFF_XD);
    u64*   cp    = (u64*)(sm + OFF_CP);
    float* S     = (float*)(sm + OFF_S);

    int tid = threadIdx.x;
    int r = tid >> 4;        // point-group row 0..15  (points r*8 .. r*8+7)
    int j = tid & 15;        // cluster-group col 0..15 (clusters j*8 .. j*8+7)

    if (mode == 0 && tid < KC) csq_s[tid] = g_csq[set][tid];

    const float* __restrict__ cent = g_cent[set];
    int tile0 = blockIdx.x * TILE_M;

    u64 acc[8][4];
    #pragma unroll
    for (int i = 0; i < 8; i++)
        #pragma unroll
        for (int q = 0; q < 4; q++) acc[i][q] = 0ull;

    for (int ch = 0; ch < NCHUNK; ch++) {
        int k0 = ch * DCH;

        // ---- stage xdup[d][p] = (x,x), d-major ----
        #pragma unroll
        for (int t = 0; t < 4; t++) {
            int idx = tid + 256 * t;            // 0..1023
            int p = idx >> 3;
            int d4 = (idx & 7) * 4;
            int pc = tile0 + p; if (pc >= N) pc = N - 1;
            float4 v = *(const float4*)(x + (size_t)pc * DC + k0 + d4);
            xd[(d4 + 0) * 128 + p] = pack2(v.x, v.x);
            xd[(d4 + 1) * 128 + p] = pack2(v.y, v.y);
            xd[(d4 + 2) * 128 + p] = pack2(v.z, v.z);
            xd[(d4 + 3) * 128 + p] = pack2(v.w, v.w);
        }
        // ---- stage cpair[d][k2] = (c[2k2], c[2k2+1]), d-major (pad k2 60..63 = 0) ----
        #pragma unroll
        for (int t = 0; t < 2; t++) {
            int idx = tid + 256 * t;            // 0..511
            int k2 = idx >> 3;
            int d4 = (idx & 7) * 4;
            float4 c0 = make_float4(0.f, 0.f, 0.f, 0.f);
            float4 c1 = c0;
            if (k2 < KC / 2) {
                c0 = *(const float4*)(cent + (2 * k2)     * DC + k0 + d4);
                c1 = *(const float4*)(cent + (2 * k2 + 1) * DC + k0 + d4);
            }
            cp[(d4 + 0) * 64 + k2] = pack2(c0.x, c1.x);
            cp[(d4 + 1) * 64 + k2] = pack2(c0.y, c1.y);
            cp[(d4 + 2) * 64 + k2] = pack2(c0.z, c1.z);
            cp[(d4 + 3) * 64 + k2] = pack2(c0.w, c1.w);
        }
        __syncthreads();

        // ---- main FFMA2 loop: 32 FFMA2 + 6 LDS.128 per d per thread ----
        const u64* xdr = xd + r * 8;
        const u64* cpr = cp + j * 4;
        #pragma unroll 2
        for (int d = 0; d < DCH; d++) {
            ulonglong2 a0 = *(const ulonglong2*)(xdr + d * 128 + 0);
            ulonglong2 a1 = *(const ulonglong2*)(xdr + d * 128 + 2);
            ulonglong2 a2 = *(const ulonglong2*)(xdr + d * 128 + 4);
            ulonglong2 a3 = *(const ulonglong2*)(xdr + d * 128 + 6);
            ulonglong2 b0 = *(const ulonglong2*)(cpr + d * 64 + 0);
            ulonglong2 b1 = *(const ulonglong2*)(cpr + d * 64 + 2);
            u64 av[8] = {a0.x, a0.y, a1.x, a1.y, a2.x, a2.y, a3.x, a3.y};
            u64 bv[4] = {b0.x, b0.y, b1.x, b1.y};
            #pragma unroll
            for (int i = 0; i < 8; i++)
                #pragma unroll
                for (int q = 0; q < 4; q++)
                    fma2(acc[i][q], av[i], bv[q]);
        }
        __syncthreads();
    }

    // ---- spill dots to S[p][k] (only k < 120) ----
    if (j < 15) {
        #pragma unroll
        for (int i = 0; i < 8; i++) {
            int p = r * 8 + i;
            #pragma unroll
            for (int q = 0; q < 4; q++) {
                float2 v = unpack2(acc[i][q]);
                int k = j * 8 + 2 * q;
                S[p * SROW + k]     = v.x;
                S[p * SROW + k + 1] = v.y;
            }
        }
    }
    __syncthreads();

    // ---- head: one thread per point (threads 0..127) ----
    int p = tile0 + tid;
    bool valid = (tid < TILE_M) && (p < N);

    if (mode == 0) {
        if (valid) {
            const float* Sp = S + tid * SROW;
            float best = FLT_MAX;
            int bi = 0;
            #pragma unroll 4
            for (int k = 0; k < KC; k++) {
                float dist = csq_s[k] - 2.0f * Sp[k];
                if (dist < best) { best = dist; bi = k; }   // strict < => first-index ties
            }
            g_labels[set][p] = bi;
        }
    } else {
        float ce = 0.0f;
        if (valid) {
            const float* Sp = S + tid * SROW;
            int lab = g_labels[set][p];
            float m = -3.0e38f, ss = 0.0f, lgl = 0.0f;
            #pragma unroll 4
            for (int k = 0; k < KC; k++) {
                float lg = 2.5f * Sp[k];          // / CLD_T = 0.4
                if (k == lab) lgl = lg;
                float nm = fmaxf(m, lg);
                ss = ss * __expf(m - nm) + __expf(lg - nm);
                m = nm;
            }
            ce = m + logf(ss) - lgl;
        }
        #pragma unroll
        for (int o = 16; o > 0; o >>= 1) ce += __shfl_down_sync(0xffffffffu, ce, o);
        float* red = (float*)(sm + OFF_RED);
        if ((tid & 31) == 0) red[tid >> 5] = ce;
        __syncthreads();
        if (tid == 0) {
            float t = red[0] + red[1] + red[2] + red[3] +
                      red[4] + red[5] + red[6] + red[7];
            atomicAdd(&g_acc[aidx], (double)t);
        }
    }
}

// ================= centroid init / update =================
__global__ void centroid_kernel(const float* __restrict__ x, int set, int mode) {
    int k = blockIdx.x;
    int d = threadIdx.x;
    float c;
    if (mode == 0) {
        c = x[k * DC + d];
    } else {
        float cnt = g_counts[k];
        if (cnt == 0.0f) cnt = 1.0f;
        c = g_sums[k * DC + d] / cnt;
    }
    g_cent[set][k * DC + d] = c;
    g_sums[k * DC + d] = 0.0f;
    if (d == 0) g_counts[k] = 0.0f;

    float v = c * c;
    #pragma unroll
    for (int o = 16; o > 0; o >>= 1) v += __shfl_down_sync(0xffffffffu, v, o);
    __shared__ float rsm[4];
    if ((d & 31) == 0) rsm[d >> 5] = v;
    __syncthreads();
    if (d == 0) g_csq[set][k] = rsm[0] + rsm[1] + rsm[2] + rsm[3];
}

// ================= scatter reduce =================
__global__ __launch_bounds__(256, 1)
void reduce_kernel(const float* __restrict__ x, int set, int N) {
    float* smf = (float*)dyn_smem;
    float* sumA = smf;
    float* sumB = smf + KC * DC;
    float* scnt = smf + 2 * KC * DC;

    int tid = threadIdx.x;
    for (int i = tid; i < 2 * KC * DC; i += 256) smf[i] = 0.0f;
    for (int i = tid; i < KC; i += 256) scnt[i] = 0.0f;
    __syncthreads();

    const int* __restrict__ lab = g_labels[set];
    int G = gridDim.x;
    int per = (N + G - 1) / G;
    int p0 = blockIdx.x * per;
    int p1 = min(N, p0 + per);

    int half = tid >> 7;
    int d = tid & 127;
    float* mysum = half ? sumB : sumA;
    int pm = p0 + ((p1 - p0) >> 1);
    int qs = half ? pm : p0;
    int qe = half ? p1 : pm;

    int p = qs;
    for (; p + 4 <= qe; p += 4) {
        int l0 = lab[p], l1 = lab[p + 1], l2 = lab[p + 2], l3 = lab[p + 3];
        float v0 = x[(size_t)(p)     * DC + d];
        float v1 = x[(size_t)(p + 1) * DC + d];
        float v2 = x[(size_t)(p + 2) * DC + d];
        float v3 = x[(size_t)(p + 3) * DC + d];
        mysum[l0 * DC + d] += v0;
        mysum[l1 * DC + d] += v1;
        mysum[l2 * DC + d] += v2;
        mysum[l3 * DC + d] += v3;
    }
    for (; p < qe; ++p)
        mysum[lab[p] * DC + d] += x[(size_t)p * DC + d];

    for (int q = p0 + tid; q < p1; q += 256)
        atomicAdd(&scnt[lab[q]], 1.0f);
    __syncthreads();

    for (int i = tid; i < KC * DC; i += 256)
        atomicAdd(&g_sums[i], sumA[i] + sumB[i]);
    for (int i = tid; i < KC; i += 256)
        atomicAdd(&g_counts[i], scnt[i]);
}

__global__ void zero_acc_kernel() {
    if (threadIdx.x < 2) g_acc[threadIdx.x] = 0.0;
}
__global__ void finalize_kernel(float* out, int N) {
    out[0] = (float)((g_acc[0] + g_acc[1]) / (2.0 * (double)N));
}

// ================= launch =================
extern "C" void kernel_launch(void* const* d_in, const int* in_sizes, int n_in,
                              void* d_out, int out_size) {
    const float* f1 = (const float*)d_in[0];
    const float* f2 = (const float*)d_in[1];
    int N = in_sizes[0] / DC;

    const int REDUCE_SMEM = (2 * KC * DC + KC) * (int)sizeof(float);

    cudaFuncSetAttribute(gemm_head_kernel, cudaFuncAttributeMaxDynamicSharedMemorySize, GEMM_SMEM);
    cudaFuncSetAttribute(reduce_kernel, cudaFuncAttributeMaxDynamicSharedMemorySize, REDUCE_SMEM);

    int ggrid = (N + TILE_M - 1) / TILE_M;

    for (int s = 0; s < 2; ++s) {
        const float* x = s ? f2 : f1;
        centroid_kernel<<<KC, DC>>>(x, s, 0);
        for (int it = 0; it < 5; ++it) {
            gemm_head_kernel<<<ggrid, 256, GEMM_SMEM>>>(x, s, 0, 0, N);
            reduce_kernel<<<128, 256, REDUCE_SMEM>>>(x, s, N);
            centroid_kernel<<<KC, DC>>>(nullptr, s, 1);
        }
    }
    zero_acc_kernel<<<1, 32>>>();
    gemm_head_kernel<<<ggrid, 256, GEMM_SMEM>>>(f1, 1, 1, 0, N);  // f1 vs c2/cl2
    gemm_head_kernel<<<ggrid, 256, GEMM_SMEM>>>(f2, 0, 1, 1, N);  // f2 vs c1/cl1
    finalize_kernel<<<1, 1>>>((float*)d_out, N);
}

// round 10
// speedup vs baseline: 1.9696x; 1.9696x over previous
#include <cuda_runtime.h>
#include <cuda_fp16.h>
#include <cstdint>
#include <cfloat>

#define KC 120
#define DC 128
#define NMAX 262144
#define TILE_M 128
#define SROW 121          // S row stride (floats), odd => conflict-free
#define KCH2 64           // dims per staging chunk
#define XST 72            // f16 row stride (64 + 8 pad) => conflict-free frag loads

typedef unsigned long long u64;

// ---------------- device scratch ----------------
__device__ float  g_cent[2][KC * DC];
__device__ float  g_csq[2][KC];
__device__ float  g_sums[KC * DC];
__device__ float  g_counts[KC];
__device__ int    g_labels[2][NMAX];
__device__ double g_acc[2];

// single dynamic-smem symbol shared by all kernels (cast locally)
extern __shared__ char dyn_smem[];

// ---------------- smem layout (gemm kernel) ----------------
#define OFF_CSQ 0                       // 128 floats
#define OFF_RED 512                     // 8 floats
#define OFF_XH  1024                    // 128 x 72 f16 = 18432 B
#define OFF_XL  (1024 + 18432)
#define OFF_CH  (1024 + 2 * 18432)
#define OFF_CL  (1024 + 3 * 18432)
#define OFF_S   1024                    // epilogue S overlaps staging
#define GEMM_SMEM (1024 + 4 * 18432)    // 74752 B

// m16n8k16 f16 mma, fp32 accumulate
__device__ __forceinline__ void mma16816(float* c, const uint32_t* a,
                                         uint32_t b0, uint32_t b1) {
    asm volatile(
        "mma.sync.aligned.m16n8k16.row.col.f32.f16.f16.f32 "
        "{%0,%1,%2,%3}, {%4,%5,%6,%7}, {%8,%9}, {%0,%1,%2,%3};"
        : "+f"(c[0]), "+f"(c[1]), "+f"(c[2]), "+f"(c[3])
        : "r"(a[0]), "r"(a[1]), "r"(a[2]), "r"(a[3]), "r"(b0), "r"(b1));
}

// ================= fp16-split tensor-core GEMM + head =================
// dot[p][k] = x_p . c_k for a 128-point tile vs 120 centroids (pad to 128).
// mode 0: argmin_k (csq[k] - 2*dot) -> g_labels[set]
// mode 1: CE_i = logsumexp(2.5*dot) - 2.5*dot[lab_i], summed -> g_acc[aidx]
__global__ __launch_bounds__(256, 2)
void gemm_head_kernel(const float* __restrict__ x, int set, int mode, int aidx, int N) {
    char* sm = dyn_smem;
    float*  csq_s = (float*)(sm + OFF_CSQ);
    __half* xh = (__half*)(sm + OFF_XH);
    __half* xl = (__half*)(sm + OFF_XL);
    __half* chh = (__half*)(sm + OFF_CH);
    __half* cll = (__half*)(sm + OFF_CL);
    float*  S  = (float*)(sm + OFF_S);

    int tid = threadIdx.x;
    int lane = tid & 31, g = lane >> 2, t = lane & 3;
    int warp = tid >> 5;
    int wm = warp >> 1;            // 0..3  -> rows wm*32
    int wn = warp & 1;             // 0..1  -> cols wn*64
    int pm = wm * 32;
    int nb = wn * 64;

    if (mode == 0 && tid < KC) csq_s[tid] = g_csq[set][tid];

    const float* __restrict__ cent = g_cent[set];
    int tile0 = blockIdx.x * TILE_M;

    float acc[2][8][4];
    #pragma unroll
    for (int mi = 0; mi < 2; mi++)
        #pragma unroll
        for (int ni = 0; ni < 8; ni++)
            #pragma unroll
            for (int q = 0; q < 4; q++) acc[mi][ni][q] = 0.0f;

    const uint32_t* XH32 = (const uint32_t*)xh;
    const uint32_t* XL32 = (const uint32_t*)xl;
    const uint32_t* CH32 = (const uint32_t*)chh;
    const uint32_t* CL32 = (const uint32_t*)cll;

    for (int ch = 0; ch < 2; ch++) {
        int k0 = ch * KCH2;

        // ---- stage X chunk: 128 rows x 64 dims, hi/lo fp16 split ----
        #pragma unroll
        for (int it = 0; it < 8; it++) {
            int idx = tid + 256 * it;           // 0..2047 float4 slots
            int p = idx >> 4, k = (idx & 15) * 4;
            int pc = tile0 + p; if (pc >= N) pc = N - 1;
            float4 v = *(const float4*)(x + (size_t)pc * DC + k0 + k);
            __half hx = __float2half_rn(v.x), hy = __float2half_rn(v.y);
            __half hz = __float2half_rn(v.z), hw = __float2half_rn(v.w);
            __half2* dh = (__half2*)(xh + p * XST + k);
            dh[0] = __halves2half2(hx, hy);
            dh[1] = __halves2half2(hz, hw);
            __half2* dl = (__half2*)(xl + p * XST + k);
            dl[0] = __halves2half2(__float2half_rn(v.x - __half2float(hx)),
                                   __float2half_rn(v.y - __half2float(hy)));
            dl[1] = __halves2half2(__float2half_rn(v.z - __half2float(hz)),
                                   __float2half_rn(v.w - __half2float(hw)));
        }
        // ---- stage C chunk: 120 rows (+8 zero pad) x 64 dims ----
        #pragma unroll
        for (int it = 0; it < 8; it++) {
            int idx = tid + 256 * it;
            int n = idx >> 4, k = (idx & 15) * 4;
            float4 v = make_float4(0.f, 0.f, 0.f, 0.f);
            if (n < KC) v = *(const float4*)(cent + n * DC + k0 + k);
            __half hx = __float2half_rn(v.x), hy = __float2half_rn(v.y);
            __half hz = __float2half_rn(v.z), hw = __float2half_rn(v.w);
            __half2* dh = (__half2*)(chh + n * XST + k);
            dh[0] = __halves2half2(hx, hy);
            dh[1] = __halves2half2(hz, hw);
            __half2* dl = (__half2*)(cll + n * XST + k);
            dl[0] = __halves2half2(__float2half_rn(v.x - __half2float(hx)),
                                   __float2half_rn(v.y - __half2float(hy)));
            dl[1] = __halves2half2(__float2half_rn(v.z - __half2float(hz)),
                                   __float2half_rn(v.w - __half2float(hw)));
        }
        __syncthreads();

        // ---- mma over 4 k-steps of 16 ----
        #pragma unroll
        for (int ks = 0; ks < 4; ks++) {
            int kk = ks * 16;
            uint32_t ah[2][4], al[2][4];
            #pragma unroll
            for (int mi = 0; mi < 2; mi++) {
                int p0 = pm + mi * 16 + g;
                int i00 = p0 * (XST / 2) + (kk + 2 * t) / 2;   // u32 units
                int i80 = i00 + 8 * (XST / 2);
                ah[mi][0] = XH32[i00];     ah[mi][1] = XH32[i80];
                ah[mi][2] = XH32[i00 + 4]; ah[mi][3] = XH32[i80 + 4];
                al[mi][0] = XL32[i00];     al[mi][1] = XL32[i80];
                al[mi][2] = XL32[i00 + 4]; al[mi][3] = XL32[i80 + 4];
            }
            #pragma unroll
            for (int ni = 0; ni < 8; ni++) {
                int n = nb + ni * 8 + g;
                int j0 = n * (XST / 2) + (kk + 2 * t) / 2;
                uint32_t bh0 = CH32[j0], bh1 = CH32[j0 + 4];
                uint32_t bl0 = CL32[j0], bl1 = CL32[j0 + 4];
                #pragma unroll
                for (int mi = 0; mi < 2; mi++) {
                    mma16816(acc[mi][ni], ah[mi], bh0, bh1);   // hi*hi
                    mma16816(acc[mi][ni], ah[mi], bl0, bl1);   // hi*lo
                    mma16816(acc[mi][ni], al[mi], bh0, bh1);   // lo*hi
                }
            }
        }
        __syncthreads();   // staging region about to be reused
    }

    // ---- write S[p][n] (skip pad cols 120..127: wn==1 && ni==7) ----
    #pragma unroll
    for (int mi = 0; mi < 2; mi++) {
        int p0 = pm + mi * 16 + g;
        #pragma unroll
        for (int ni = 0; ni < 8; ni++) {
            if (wn == 1 && ni == 7) continue;
            int n0 = nb + ni * 8 + 2 * t;
            S[p0 * SROW + n0]           = acc[mi][ni][0];
            S[p0 * SROW + n0 + 1]       = acc[mi][ni][1];
            S[(p0 + 8) * SROW + n0]     = acc[mi][ni][2];
            S[(p0 + 8) * SROW + n0 + 1] = acc[mi][ni][3];
        }
    }
    __syncthreads();

    // ---- head: one thread per point (threads 0..127) ----
    int p = tile0 + tid;
    bool valid = (tid < TILE_M) && (p < N);

    if (mode == 0) {
        if (valid) {
            const float* Sp = S + tid * SROW;
            float best = FLT_MAX;
            int bi = 0;
            #pragma unroll 4
            for (int k = 0; k < KC; k++) {
                float dist = csq_s[k] - 2.0f * Sp[k];
                if (dist < best) { best = dist; bi = k; }   // strict < => first-index ties
            }
            g_labels[set][p] = bi;
        }
    } else {
        float ce = 0.0f;
        if (valid) {
            const float* Sp = S + tid * SROW;
            int lab = g_labels[set][p];
            float m = -3.0e38f, ss = 0.0f, lgl = 0.0f;
            #pragma unroll 4
            for (int k = 0; k < KC; k++) {
                float lg = 2.5f * Sp[k];          // / CLD_T = 0.4
                if (k == lab) lgl = lg;
                float nm = fmaxf(m, lg);
                ss = ss * __expf(m - nm) + __expf(lg - nm);
                m = nm;
            }
            ce = m + logf(ss) - lgl;
        }
        #pragma unroll
        for (int o = 16; o > 0; o >>= 1) ce += __shfl_down_sync(0xffffffffu, ce, o);
        float* red = (float*)(sm + OFF_RED);
        if ((tid & 31) == 0) red[tid >> 5] = ce;
        __syncthreads();
        if (tid == 0) {
            float tt = red[0] + red[1] + red[2] + red[3] +
                       red[4] + red[5] + red[6] + red[7];
            atomicAdd(&g_acc[aidx], (double)tt);
        }
    }
}

// ================= centroid init / update =================
__global__ void centroid_kernel(const float* __restrict__ x, int set, int mode) {
    int k = blockIdx.x;
    int d = threadIdx.x;
    float c;
    if (mode == 0) {
        c = x[k * DC + d];
    } else {
        float cnt = g_counts[k];
        if (cnt == 0.0f) cnt = 1.0f;
        c = g_sums[k * DC + d] / cnt;
    }
    g_cent[set][k * DC + d] = c;
    g_sums[k * DC + d] = 0.0f;
    if (d == 0) g_counts[k] = 0.0f;

    float v = c * c;
    #pragma unroll
    for (int o = 16; o > 0; o >>= 1) v += __shfl_down_sync(0xffffffffu, v, o);
    __shared__ float rsm[4];
    if ((d & 31) == 0) rsm[d >> 5] = v;
    __syncthreads();
    if (d == 0) g_csq[set][k] = rsm[0] + rsm[1] + rsm[2] + rsm[3];
}

// ================= scatter reduce =================
__global__ __launch_bounds__(256, 1)
void reduce_kernel(const float* __restrict__ x, int set, int N) {
    float* smf = (float*)dyn_smem;
    float* sumA = smf;
    float* sumB = smf + KC * DC;
    float* scnt = smf + 2 * KC * DC;

    int tid = threadIdx.x;
    for (int i = tid; i < 2 * KC * DC; i += 256) smf[i] = 0.0f;
    for (int i = tid; i < KC; i += 256) scnt[i] = 0.0f;
    __syncthreads();

    const int* __restrict__ lab = g_labels[set];
    int G = gridDim.x;
    int per = (N + G - 1) / G;
    int p0 = blockIdx.x * per;
    int p1 = min(N, p0 + per);

    int half = tid >> 7;
    int d = tid & 127;
    float* mysum = half ? sumB : sumA;
    int pm = p0 + ((p1 - p0) >> 1);
    int qs = half ? pm : p0;
    int qe = half ? p1 : pm;

    int p = qs;
    for (; p + 4 <= qe; p += 4) {
        int l0 = lab[p], l1 = lab[p + 1], l2 = lab[p + 2], l3 = lab[p + 3];
        float v0 = x[(size_t)(p)     * DC + d];
        float v1 = x[(size_t)(p + 1) * DC + d];
        float v2 = x[(size_t)(p + 2) * DC + d];
        float v3 = x[(size_t)(p + 3) * DC + d];
        mysum[l0 * DC + d] += v0;
        mysum[l1 * DC + d] += v1;
        mysum[l2 * DC + d] += v2;
        mysum[l3 * DC + d] += v3;
    }
    for (; p < qe; ++p)
        mysum[lab[p] * DC + d] += x[(size_t)p * DC + d];

    for (int q = p0 + tid; q < p1; q += 256)
        atomicAdd(&scnt[lab[q]], 1.0f);
    __syncthreads();

    for (int i = tid; i < KC * DC; i += 256)
        atomicAdd(&g_sums[i], sumA[i] + sumB[i]);
    for (int i = tid; i < KC; i += 256)
        atomicAdd(&g_counts[i], scnt[i]);
}

__global__ void zero_acc_kernel() {
    if (threadIdx.x < 2) g_acc[threadIdx.x] = 0.0;
}
__global__ void finalize_kernel(float* out, int N) {
    out[0] = (float)((g_acc[0] + g_acc[1]) / (2.0 * (double)N));
}

// ================= launch =================
extern "C" void kernel_launch(void* const* d_in, const int* in_sizes, int n_in,
                              void* d_out, int out_size) {
    const float* f1 = (const float*)d_in[0];
    const float* f2 = (const float*)d_in[1];
    int N = in_sizes[0] / DC;

    const int REDUCE_SMEM = (2 * KC * DC + KC) * (int)sizeof(float);

    cudaFuncSetAttribute(gemm_head_kernel, cudaFuncAttributeMaxDynamicSharedMemorySize, GEMM_SMEM);
    cudaFuncSetAttribute(reduce_kernel, cudaFuncAttributeMaxDynamicSharedMemorySize, REDUCE_SMEM);

    int ggrid = (N + TILE_M - 1) / TILE_M;

    for (int s = 0; s < 2; ++s) {
        const float* x = s ? f2 : f1;
        centroid_kernel<<<KC, DC>>>(x, s, 0);
        for (int it = 0; it < 5; ++it) {
            gemm_head_kernel<<<ggrid, 256, GEMM_SMEM>>>(x, s, 0, 0, N);
            reduce_kernel<<<128, 256, REDUCE_SMEM>>>(x, s, N);
            centroid_kernel<<<KC, DC>>>(nullptr, s, 1);
        }
    }
    zero_acc_kernel<<<1, 32>>>();
    gemm_head_kernel<<<ggrid, 256, GEMM_SMEM>>>(f1, 1, 1, 0, N);  // f1 vs c2/cl2
    gemm_head_kernel<<<ggrid, 256, GEMM_SMEM>>>(f2, 0, 1, 1, N);  // f2 vs c1/cl1
    finalize_kernel<<<1, 1>>>((float*)d_out, N);
}